// round 2
// baseline (speedup 1.0000x reference)
#include <cuda_runtime.h>
#include <cstddef>

#define D1 128
#define D2 64
#define MAXN 50176

// Scratch (allocation-free rule: __device__ globals)
__device__ float g_h1  [MAXN * D1];   // x @ W1
__device__ float g_agg1[MAXN * D1];   // layer-1 aggregation -> relu'd layer-2 input (in place)
__device__ float g_h2  [MAXN * D2];   // agg1 @ W2
__device__ int   g_deg [MAXN];
__device__ float g_dis [MAXN];

// ---------------------------------------------------------------------------
// Zero agg1, d_out, deg in one pass
// ---------------------------------------------------------------------------
__global__ void zero_kernel(float4* __restrict__ dout, int n) {
    int i = blockIdx.x * blockDim.x + threadIdx.x;
    int n1 = n * 32;           // agg1 as float4
    int n2 = n * 16;           // dout as float4
    float4 z = make_float4(0.f, 0.f, 0.f, 0.f);
    if (i < n1) {
        ((float4*)g_agg1)[i] = z;
    } else if (i < n1 + n2) {
        dout[i - n1] = z;
    } else if (i < n1 + n2 + n) {
        g_deg[i - n1 - n2] = 0;
    }
}

// ---------------------------------------------------------------------------
// Destination degree (real edges only; +1 self-loop added in dis_kernel)
// ---------------------------------------------------------------------------
__global__ void deg_kernel(const int* __restrict__ col, int E) {
    int e = blockIdx.x * blockDim.x + threadIdx.x;
    if (e < E) atomicAdd(&g_deg[col[e]], 1);
}

__global__ void dis_kernel(int n) {
    int i = blockIdx.x * blockDim.x + threadIdx.x;
    if (i < n) g_dis[i] = rsqrtf((float)(g_deg[i] + 1));
}

// ---------------------------------------------------------------------------
// Tiled SGEMM: H[n, DOUT] = X[n, 128] @ W[128, DOUT]
// LAYER=1: X = x (param), H = g_h1.  LAYER=2: X = g_agg1, H = g_h2.
// BM=64, BK=32, 256 threads, 4xTC register tile (TC = DOUT/16).
// ---------------------------------------------------------------------------
template <int DOUT, int LAYER>
__global__ void gemm_kernel(const float* __restrict__ Xp, const float* __restrict__ W, int n) {
    constexpr int BM = 64, BK = 32, K = 128;
    constexpr int TC = DOUT / 16;            // 8 (D1) or 4 (D2)
    __shared__ float Xs[BM * BK];
    __shared__ float Ws[BK * DOUT];

    const float* X = (LAYER == 1) ? Xp : g_agg1;
    float*       H = (LAYER == 1) ? g_h1 : g_h2;

    int tid = threadIdx.x;                   // 256 threads
    int tx = tid & 15;
    int ty = tid >> 4;
    int row0 = blockIdx.x * BM;

    float acc[4][TC];
#pragma unroll
    for (int i = 0; i < 4; i++)
#pragma unroll
        for (int j = 0; j < TC; j++) acc[i][j] = 0.f;

    for (int k0 = 0; k0 < K; k0 += BK) {
        // Stage X tile: 64x32 floats, 8 per thread (2x float4)
        {
            int r  = tid >> 2;
            int kk = (tid & 3) * 8;
            int gr = row0 + r;
            float4 a0 = make_float4(0.f, 0.f, 0.f, 0.f), a1 = a0;
            if (gr < n) {
                const float4* p = (const float4*)(X + (size_t)gr * K + k0 + kk);
                a0 = p[0]; a1 = p[1];
            }
            *(float4*)(Xs + r * BK + kk)     = a0;
            *(float4*)(Xs + r * BK + kk + 4) = a1;
        }
        // Stage W tile: 32xDOUT floats
        {
            constexpr int VPT = (BK * DOUT) / (256 * 4);   // float4s per thread
            int e = tid * VPT * 4;
#pragma unroll
            for (int v = 0; v < VPT; v++) {
                int kk = e / DOUT, c = e % DOUT;
                *(float4*)(Ws + kk * DOUT + c) =
                    *(const float4*)(W + (size_t)(k0 + kk) * DOUT + c);
                e += 4;
            }
        }
        __syncthreads();
#pragma unroll
        for (int kk = 0; kk < BK; kk++) {
            float a[4], b[TC];
#pragma unroll
            for (int i = 0; i < 4; i++) a[i] = Xs[(ty * 4 + i) * BK + kk];
#pragma unroll
            for (int j = 0; j < TC; j++) b[j] = Ws[kk * DOUT + tx * TC + j];
#pragma unroll
            for (int i = 0; i < 4; i++)
#pragma unroll
                for (int j = 0; j < TC; j++) acc[i][j] += a[i] * b[j];
        }
        __syncthreads();
    }
#pragma unroll
    for (int i = 0; i < 4; i++) {
        int gr = row0 + ty * 4 + i;
        if (gr < n) {
#pragma unroll
            for (int j = 0; j < TC; j += 4) {
                float4 v = make_float4(acc[i][j], acc[i][j + 1], acc[i][j + 2], acc[i][j + 3]);
                *(float4*)(H + (size_t)gr * DOUT + tx * TC + j) = v;
            }
        }
    }
}

// ---------------------------------------------------------------------------
// Edge scatter, layer 1: warp per edge, lane handles 4 floats (128 total).
// Vector reduction atomics: red.global.add.v4.f32
// ---------------------------------------------------------------------------
__global__ void scatter1_kernel(const int* __restrict__ row, const int* __restrict__ col, int E) {
    int t = blockIdx.x * blockDim.x + threadIdx.x;
    int e = t >> 5;
    if (e >= E) return;
    int lane = t & 31;
    int r = __ldg(row + e);
    int c = __ldg(col + e);
    float w = g_dis[r] * g_dis[c];
    float4 v = ((const float4*)(g_h1 + (size_t)r * D1))[lane];
    float* dst = g_agg1 + (size_t)c * D1 + lane * 4;
    asm volatile("red.global.add.v4.f32 [%0], {%1, %2, %3, %4};"
                 :: "l"(dst), "f"(v.x * w), "f"(v.y * w), "f"(v.z * w), "f"(v.w * w)
                 : "memory");
}

// Edge scatter, layer 2: 16 lanes per edge (64 floats), straight into d_out.
__global__ void scatter2_kernel(const int* __restrict__ row, const int* __restrict__ col,
                                float* __restrict__ dout, int E) {
    int t = blockIdx.x * blockDim.x + threadIdx.x;
    int e = t >> 4;
    if (e >= E) return;
    int lane = t & 15;
    int r = __ldg(row + e);
    int c = __ldg(col + e);
    float w = g_dis[r] * g_dis[c];
    float4 v = ((const float4*)(g_h2 + (size_t)r * D2))[lane];
    float* dst = dout + (size_t)c * D2 + lane * 4;
    asm volatile("red.global.add.v4.f32 [%0], {%1, %2, %3, %4};"
                 :: "l"(dst), "f"(v.x * w), "f"(v.y * w), "f"(v.z * w), "f"(v.w * w)
                 : "memory");
}

// ---------------------------------------------------------------------------
// Epilogue 1: agg1 = relu(agg1 + h1*dis^2 + b1)   (self-loop folded in)
// ---------------------------------------------------------------------------
__global__ void post1_kernel(const float* __restrict__ b1, int n) {
    int idx = blockIdx.x * blockDim.x + threadIdx.x;
    if (idx >= n * 32) return;
    int i = idx >> 5, j = idx & 31;
    float d2 = g_dis[i] * g_dis[i];
    float4 a = ((float4*)g_agg1)[idx];
    float4 h = ((const float4*)g_h1)[idx];
    float4 b = ((const float4*)b1)[j];
    float4 r;
    r.x = fmaxf(fmaf(h.x, d2, a.x) + b.x, 0.f);
    r.y = fmaxf(fmaf(h.y, d2, a.y) + b.y, 0.f);
    r.z = fmaxf(fmaf(h.z, d2, a.z) + b.z, 0.f);
    r.w = fmaxf(fmaf(h.w, d2, a.w) + b.w, 0.f);
    ((float4*)g_agg1)[idx] = r;
}

// Epilogue 2: d_out += h2*dis^2 + b2   (no relu on final layer)
__global__ void post2_kernel(const float* __restrict__ b2, float4* __restrict__ dout, int n) {
    int idx = blockIdx.x * blockDim.x + threadIdx.x;
    if (idx >= n * 16) return;
    int i = idx >> 4, j = idx & 15;
    float d2 = g_dis[i] * g_dis[i];
    float4 a = dout[idx];
    float4 h = ((const float4*)g_h2)[idx];
    float4 b = ((const float4*)b2)[j];
    a.x = fmaf(h.x, d2, a.x) + b.x;
    a.y = fmaf(h.y, d2, a.y) + b.y;
    a.z = fmaf(h.z, d2, a.z) + b.z;
    a.w = fmaf(h.w, d2, a.w) + b.w;
    dout[idx] = a;
}

// ---------------------------------------------------------------------------
extern "C" void kernel_launch(void* const* d_in, const int* in_sizes, int n_in,
                              void* d_out, int out_size) {
    const float* x  = (const float*)d_in[0];
    const int*   ei = (const int*)  d_in[1];
    const float* W1 = (const float*)d_in[2];
    const float* b1 = (const float*)d_in[3];
    const float* W2 = (const float*)d_in[4];
    const float* b2 = (const float*)d_in[5];
    float* out = (float*)d_out;

    int n = in_sizes[0] / D1;
    int E = in_sizes[1] / 2;
    const int* row = ei;
    const int* col = ei + E;

    const int TB = 256;
    zero_kernel<<<(n * 49 + TB - 1) / TB, TB>>>((float4*)out, n);
    deg_kernel<<<(E + TB - 1) / TB, TB>>>(col, E);
    dis_kernel<<<(n + TB - 1) / TB, TB>>>(n);

    gemm_kernel<D1, 1><<<(n + 63) / 64, TB>>>(x, W1, n);
    scatter1_kernel<<<(int)(((long long)E * 32 + TB - 1) / TB), TB>>>(row, col, E);
    post1_kernel<<<(n * 32 + TB - 1) / TB, TB>>>(b1, n);

    gemm_kernel<D2, 2><<<(n + 63) / 64, TB>>>(nullptr, W2, n);
    scatter2_kernel<<<(int)(((long long)E * 16 + TB - 1) / TB), TB>>>(row, col, out, E);
    post2_kernel<<<(n * 16 + TB - 1) / TB, TB>>>(b2, (float4*)out, n);
}

// round 3
// speedup vs baseline: 1.1373x; 1.1373x over previous
#include <cuda_runtime.h>
#include <cstddef>

#define D1 128
#define D2 64
#define MAXN 50176

// Scratch (allocation-free rule: __device__ globals)
__device__ float g_h1  [MAXN * D1];   // x @ W1
__device__ float g_agg1[MAXN * D1];   // layer-1 aggregation -> relu'd layer-2 input (in place)
__device__ float g_h2  [MAXN * D2];   // agg1 @ W2
__device__ int   g_deg [MAXN];
__device__ float g_dis [MAXN];

// ---------------------------------------------------------------------------
// Zero agg1, d_out, deg in one pass
// ---------------------------------------------------------------------------
__global__ void zero_kernel(float4* __restrict__ dout, int n) {
    int i = blockIdx.x * blockDim.x + threadIdx.x;
    int n1 = n * 32;           // agg1 as float4
    int n2 = n * 16;           // dout as float4
    float4 z = make_float4(0.f, 0.f, 0.f, 0.f);
    if (i < n1) {
        ((float4*)g_agg1)[i] = z;
    } else if (i < n1 + n2) {
        dout[i - n1] = z;
    } else if (i < n1 + n2 + n) {
        g_deg[i - n1 - n2] = 0;
    }
}

__global__ void deg_kernel(const int* __restrict__ col, int E) {
    int e = blockIdx.x * blockDim.x + threadIdx.x;
    if (e < E) atomicAdd(&g_deg[col[e]], 1);
}

__global__ void dis_kernel(int n) {
    int i = blockIdx.x * blockDim.x + threadIdx.x;
    if (i < n) g_dis[i] = rsqrtf((float)(g_deg[i] + 1));
}

// ---------------------------------------------------------------------------
// SGEMM: H[n, BN] = X[n, 128] @ W[128, BN]
// 256 threads, 8x8 per-thread register tile, conflict-free smem access,
// register prefetch of the next K-tile.
// LAYER=1: X = x (param), H = g_h1.  LAYER=2: X = g_agg1, H = g_h2.
// ---------------------------------------------------------------------------
template <int BM, int BN, int BK, int LAYER>
__global__ void __launch_bounds__(256, 2)
sgemm_kernel(const float* __restrict__ Xp, const float* __restrict__ W, int n) {
    constexpr int K = 128;
    constexpr int NT = K / BK;                 // K tiles
    constexpr int NTHREADS = 256;
    constexpr int XS = BM + 4;                 // padded Xs row stride (floats), keeps 16B align
    constexpr int XLD = BM * BK / 4 / NTHREADS;  // float4 X loads per thread
    constexpr int WLD = BK * BN / 4 / NTHREADS;  // float4 W loads per thread
    constexpr int KG = BK / 4;                 // float4 groups along K

    __shared__ float Xs[BK * XS];
    __shared__ float Ws[BK * BN];

    const float* X = (LAYER == 1) ? Xp : g_agg1;
    float*       H = (LAYER == 1) ? g_h1 : g_h2;

    int tid = threadIdx.x;
    constexpr int TXN = BN / 8;
    int tx = tid % TXN;
    int ty = tid / TXN;
    int row0 = blockIdx.x * BM;

    float acc[8][8];
#pragma unroll
    for (int i = 0; i < 8; i++)
#pragma unroll
        for (int j = 0; j < 8; j++) acc[i][j] = 0.f;

    float4 px[XLD], pw[WLD];
    const float4 z4 = make_float4(0.f, 0.f, 0.f, 0.f);

    // ---- global loads into registers ----
    auto loadX = [&](int k0) {
#pragma unroll
        for (int l = 0; l < XLD; l++) {
            int idx = tid + l * NTHREADS;
            int r = idx / KG;
            int kk4 = (idx % KG) * 4;
            int gr = row0 + r;
            px[l] = (gr < n) ? *(const float4*)(X + (size_t)gr * K + k0 + kk4) : z4;
        }
    };
    auto loadW = [&](int k0) {
#pragma unroll
        for (int l = 0; l < WLD; l++) {
            int idx = (tid + l * NTHREADS) * 4;
            int kk = idx / BN, c = idx % BN;
            pw[l] = *(const float4*)(W + (size_t)(k0 + kk) * BN + c);
        }
    };
    // ---- registers -> smem ----
    auto storeX = [&]() {
#pragma unroll
        for (int l = 0; l < XLD; l++) {
            int idx = tid + l * NTHREADS;
            int r = idx / KG;
            int kk4 = (idx % KG) * 4;
            Xs[(kk4 + 0) * XS + r] = px[l].x;
            Xs[(kk4 + 1) * XS + r] = px[l].y;
            Xs[(kk4 + 2) * XS + r] = px[l].z;
            Xs[(kk4 + 3) * XS + r] = px[l].w;
        }
    };
    auto storeW = [&]() {
#pragma unroll
        for (int l = 0; l < WLD; l++) {
            int idx = (tid + l * NTHREADS) * 4;
            int kk = idx / BN, c = idx % BN;
            *(float4*)(Ws + kk * BN + c) = pw[l];
        }
    };

    loadX(0); loadW(0);
    storeX(); storeW();
    __syncthreads();

    for (int t = 0; t < NT; t++) {
        if (t + 1 < NT) { loadX((t + 1) * BK); loadW((t + 1) * BK); }
#pragma unroll
        for (int kk = 0; kk < BK; kk++) {
            float a[8], b[8];
            *(float4*)&a[0] = *(const float4*)(Xs + kk * XS + ty * 8);
            *(float4*)&a[4] = *(const float4*)(Xs + kk * XS + ty * 8 + 4);
            *(float4*)&b[0] = *(const float4*)(Ws + kk * BN + tx * 4);
            *(float4*)&b[4] = *(const float4*)(Ws + kk * BN + BN / 2 + tx * 4);
#pragma unroll
            for (int i = 0; i < 8; i++)
#pragma unroll
                for (int j = 0; j < 8; j++) acc[i][j] = fmaf(a[i], b[j], acc[i][j]);
        }
        if (t + 1 < NT) {
            __syncthreads();
            storeX(); storeW();
            __syncthreads();
        }
    }

#pragma unroll
    for (int i = 0; i < 8; i++) {
        int gr = row0 + ty * 8 + i;
        if (gr < n) {
            float4 v0 = make_float4(acc[i][0], acc[i][1], acc[i][2], acc[i][3]);
            float4 v1 = make_float4(acc[i][4], acc[i][5], acc[i][6], acc[i][7]);
            *(float4*)(H + (size_t)gr * BN + tx * 4)          = v0;
            *(float4*)(H + (size_t)gr * BN + BN / 2 + tx * 4) = v1;
        }
    }
}

// ---------------------------------------------------------------------------
// Edge scatter, layer 1: warp per edge, lane handles 4 floats (128 total).
// ---------------------------------------------------------------------------
__global__ void scatter1_kernel(const int* __restrict__ row, const int* __restrict__ col, int E) {
    int t = blockIdx.x * blockDim.x + threadIdx.x;
    int e = t >> 5;
    if (e >= E) return;
    int lane = t & 31;
    int r = __ldg(row + e);
    int c = __ldg(col + e);
    float w = g_dis[r] * g_dis[c];
    float4 v = ((const float4*)(g_h1 + (size_t)r * D1))[lane];
    float* dst = g_agg1 + (size_t)c * D1 + lane * 4;
    asm volatile("red.global.add.v4.f32 [%0], {%1, %2, %3, %4};"
                 :: "l"(dst), "f"(v.x * w), "f"(v.y * w), "f"(v.z * w), "f"(v.w * w)
                 : "memory");
}

// Edge scatter, layer 2: 16 lanes per edge (64 floats), straight into d_out.
__global__ void scatter2_kernel(const int* __restrict__ row, const int* __restrict__ col,
                                float* __restrict__ dout, int E) {
    int t = blockIdx.x * blockDim.x + threadIdx.x;
    int e = t >> 4;
    if (e >= E) return;
    int lane = t & 15;
    int r = __ldg(row + e);
    int c = __ldg(col + e);
    float w = g_dis[r] * g_dis[c];
    float4 v = ((const float4*)(g_h2 + (size_t)r * D2))[lane];
    float* dst = dout + (size_t)c * D2 + lane * 4;
    asm volatile("red.global.add.v4.f32 [%0], {%1, %2, %3, %4};"
                 :: "l"(dst), "f"(v.x * w), "f"(v.y * w), "f"(v.z * w), "f"(v.w * w)
                 : "memory");
}

// ---------------------------------------------------------------------------
// Epilogue 1: agg1 = relu(agg1 + h1*dis^2 + b1)   (self-loop folded in)
// ---------------------------------------------------------------------------
__global__ void post1_kernel(const float* __restrict__ b1, int n) {
    int idx = blockIdx.x * blockDim.x + threadIdx.x;
    if (idx >= n * 32) return;
    int i = idx >> 5, j = idx & 31;
    float d2 = g_dis[i] * g_dis[i];
    float4 a = ((float4*)g_agg1)[idx];
    float4 h = ((const float4*)g_h1)[idx];
    float4 b = ((const float4*)b1)[j];
    float4 r;
    r.x = fmaxf(fmaf(h.x, d2, a.x) + b.x, 0.f);
    r.y = fmaxf(fmaf(h.y, d2, a.y) + b.y, 0.f);
    r.z = fmaxf(fmaf(h.z, d2, a.z) + b.z, 0.f);
    r.w = fmaxf(fmaf(h.w, d2, a.w) + b.w, 0.f);
    ((float4*)g_agg1)[idx] = r;
}

// Epilogue 2: d_out += h2*dis^2 + b2   (no relu on final layer)
__global__ void post2_kernel(const float* __restrict__ b2, float4* __restrict__ dout, int n) {
    int idx = blockIdx.x * blockDim.x + threadIdx.x;
    if (idx >= n * 16) return;
    int i = idx >> 4, j = idx & 15;
    float d2 = g_dis[i] * g_dis[i];
    float4 a = dout[idx];
    float4 h = ((const float4*)g_h2)[idx];
    float4 b = ((const float4*)b2)[j];
    a.x = fmaf(h.x, d2, a.x) + b.x;
    a.y = fmaf(h.y, d2, a.y) + b.y;
    a.z = fmaf(h.z, d2, a.z) + b.z;
    a.w = fmaf(h.w, d2, a.w) + b.w;
    dout[idx] = a;
}

// ---------------------------------------------------------------------------
extern "C" void kernel_launch(void* const* d_in, const int* in_sizes, int n_in,
                              void* d_out, int out_size) {
    const float* x  = (const float*)d_in[0];
    const int*   ei = (const int*)  d_in[1];
    const float* W1 = (const float*)d_in[2];
    const float* b1 = (const float*)d_in[3];
    const float* W2 = (const float*)d_in[4];
    const float* b2 = (const float*)d_in[5];
    float* out = (float*)d_out;

    int n = in_sizes[0] / D1;
    int E = in_sizes[1] / 2;
    const int* row = ei;
    const int* col = ei + E;

    const int TB = 256;
    zero_kernel<<<(n * 49 + TB - 1) / TB, TB>>>((float4*)out, n);
    deg_kernel<<<(E + TB - 1) / TB, TB>>>(col, E);
    dis_kernel<<<(n + TB - 1) / TB, TB>>>(n);

    sgemm_kernel<128, 128, 16, 1><<<(n + 127) / 128, TB>>>(x, W1, n);
    scatter1_kernel<<<(int)(((long long)E * 32 + TB - 1) / TB), TB>>>(row, col, E);
    post1_kernel<<<(n * 32 + TB - 1) / TB, TB>>>(b1, n);

    sgemm_kernel<256, 64, 16, 2><<<(n + 255) / 256, TB>>>(nullptr, W2, n);
    scatter2_kernel<<<(int)(((long long)E * 16 + TB - 1) / TB), TB>>>(row, col, out, E);
    post2_kernel<<<(n * 16 + TB - 1) / TB, TB>>>(b2, (float4*)out, n);
}

// round 4
// speedup vs baseline: 1.8068x; 1.5887x over previous
#include <cuda_runtime.h>
#include <cstddef>

#define D1 128
#define D2 64
#define MAXN 50176
#define MAXE 1048576
#define SCAN_B 1024

// Scratch (allocation-free rule: __device__ globals)
__device__ float g_h1  [MAXN * D1];   // (x @ W1) * dis[row]
__device__ float g_agg1[MAXN * D1];   // relu'd layer-1 output = layer-2 input
__device__ float g_h2  [MAXN * D2];   // (agg1 @ W2) * dis[row]
__device__ int   g_deg [MAXN];
__device__ float g_dis [MAXN];
__device__ int   g_scan[MAXN];        // per-chunk inclusive scan of deg
__device__ int   g_bsum[MAXN / SCAN_B + 2];
__device__ int   g_off [MAXN + 1];    // CSR offsets (by destination)
__device__ int   g_cnt [MAXN];        // fill counters
__device__ int   g_csr [MAXE];        // source node ids, sorted by destination

// ---------------------------------------------------------------------------
__global__ void zero_kernel(int n) {
    int i = blockIdx.x * blockDim.x + threadIdx.x;
    if (i < n) { g_deg[i] = 0; g_cnt[i] = 0; }
}

__global__ void deg_kernel(const int* __restrict__ col, int E) {
    int e = blockIdx.x * blockDim.x + threadIdx.x;
    if (e < E) atomicAdd(&g_deg[col[e]], 1);
}

__global__ void dis_kernel(int n) {
    int i = blockIdx.x * blockDim.x + threadIdx.x;
    if (i < n) g_dis[i] = rsqrtf((float)(g_deg[i] + 1));
}

// ---------------------------------------------------------------------------
// Exclusive scan of g_deg -> g_off  (3 small kernels)
// ---------------------------------------------------------------------------
__global__ void scan1_kernel(int n) {             // 1024 threads/block
    __shared__ int sh[SCAN_B];
    int t = threadIdx.x;
    int i = blockIdx.x * SCAN_B + t;
    int v = (i < n) ? g_deg[i] : 0;
    sh[t] = v;
    __syncthreads();
#pragma unroll
    for (int d = 1; d < SCAN_B; d <<= 1) {
        int a = (t >= d) ? sh[t - d] : 0;
        __syncthreads();
        sh[t] += a;
        __syncthreads();
    }
    if (i < n) g_scan[i] = sh[t];                 // inclusive within chunk
    if (t == SCAN_B - 1) g_bsum[blockIdx.x] = sh[t];
}

__global__ void scan2_kernel(int nb) {            // single block, 1024 threads
    __shared__ int sh[SCAN_B];
    int t = threadIdx.x;
    int v = (t < nb) ? g_bsum[t] : 0;
    sh[t] = v;
    __syncthreads();
#pragma unroll
    for (int d = 1; d < SCAN_B; d <<= 1) {
        int a = (t >= d) ? sh[t - d] : 0;
        __syncthreads();
        sh[t] += a;
        __syncthreads();
    }
    if (t < nb) g_bsum[t] = sh[t] - v;            // exclusive
}

__global__ void scan3_kernel(int n, int E) {
    int i = blockIdx.x * blockDim.x + threadIdx.x;
    if (i < n) g_off[i] = g_scan[i] - g_deg[i] + g_bsum[i / SCAN_B];
    if (i == n) g_off[n] = E;
}

__global__ void fill_kernel(const int* __restrict__ row, const int* __restrict__ col, int E) {
    int e = blockIdx.x * blockDim.x + threadIdx.x;
    if (e >= E) return;
    int c = col[e];
    int pos = g_off[c] + atomicAdd(&g_cnt[c], 1);
    g_csr[pos] = row[e];
}

// ---------------------------------------------------------------------------
// SGEMM: H[n, BN] = (X[n, 128] @ W[128, BN]) * dis[row]
// 256 threads, 8x8 register tile, register prefetch.
// LAYER=1: X = x (param), H = g_h1.  LAYER=2: X = g_agg1, H = g_h2.
// ---------------------------------------------------------------------------
template <int BM, int BN, int BK, int LAYER>
__global__ void __launch_bounds__(256, 2)
sgemm_kernel(const float* __restrict__ Xp, const float* __restrict__ W, int n) {
    constexpr int K = 128;
    constexpr int NT = K / BK;
    constexpr int NTHREADS = 256;
    constexpr int XS = BM + 4;
    constexpr int XLD = BM * BK / 4 / NTHREADS;
    constexpr int WLD = BK * BN / 4 / NTHREADS;
    constexpr int KG = BK / 4;

    __shared__ float Xs[BK * XS];
    __shared__ float Ws[BK * BN];

    const float* X = (LAYER == 1) ? Xp : g_agg1;
    float*       H = (LAYER == 1) ? g_h1 : g_h2;

    int tid = threadIdx.x;
    constexpr int TXN = BN / 8;
    int tx = tid % TXN;
    int ty = tid / TXN;
    int row0 = blockIdx.x * BM;

    float acc[8][8];
#pragma unroll
    for (int i = 0; i < 8; i++)
#pragma unroll
        for (int j = 0; j < 8; j++) acc[i][j] = 0.f;

    float4 px[XLD], pw[WLD];
    const float4 z4 = make_float4(0.f, 0.f, 0.f, 0.f);

    auto loadX = [&](int k0) {
#pragma unroll
        for (int l = 0; l < XLD; l++) {
            int idx = tid + l * NTHREADS;
            int r = idx / KG;
            int kk4 = (idx % KG) * 4;
            int gr = row0 + r;
            px[l] = (gr < n) ? *(const float4*)(X + (size_t)gr * K + k0 + kk4) : z4;
        }
    };
    auto loadW = [&](int k0) {
#pragma unroll
        for (int l = 0; l < WLD; l++) {
            int idx = (tid + l * NTHREADS) * 4;
            int kk = idx / BN, c = idx % BN;
            pw[l] = *(const float4*)(W + (size_t)(k0 + kk) * BN + c);
        }
    };
    auto storeX = [&]() {
#pragma unroll
        for (int l = 0; l < XLD; l++) {
            int idx = tid + l * NTHREADS;
            int r = idx / KG;
            int kk4 = (idx % KG) * 4;
            Xs[(kk4 + 0) * XS + r] = px[l].x;
            Xs[(kk4 + 1) * XS + r] = px[l].y;
            Xs[(kk4 + 2) * XS + r] = px[l].z;
            Xs[(kk4 + 3) * XS + r] = px[l].w;
        }
    };
    auto storeW = [&]() {
#pragma unroll
        for (int l = 0; l < WLD; l++) {
            int idx = (tid + l * NTHREADS) * 4;
            int kk = idx / BN, c = idx % BN;
            *(float4*)(Ws + kk * BN + c) = pw[l];
        }
    };

    loadX(0); loadW(0);
    storeX(); storeW();
    __syncthreads();

    for (int t = 0; t < NT; t++) {
        if (t + 1 < NT) { loadX((t + 1) * BK); loadW((t + 1) * BK); }
#pragma unroll
        for (int kk = 0; kk < BK; kk++) {
            float a[8], b[8];
            *(float4*)&a[0] = *(const float4*)(Xs + kk * XS + ty * 8);
            *(float4*)&a[4] = *(const float4*)(Xs + kk * XS + ty * 8 + 4);
            *(float4*)&b[0] = *(const float4*)(Ws + kk * BN + tx * 4);
            *(float4*)&b[4] = *(const float4*)(Ws + kk * BN + BN / 2 + tx * 4);
#pragma unroll
            for (int i = 0; i < 8; i++)
#pragma unroll
                for (int j = 0; j < 8; j++) acc[i][j] = fmaf(a[i], b[j], acc[i][j]);
        }
        if (t + 1 < NT) {
            __syncthreads();
            storeX(); storeW();
            __syncthreads();
        }
    }

#pragma unroll
    for (int i = 0; i < 8; i++) {
        int gr = row0 + ty * 8 + i;
        if (gr < n) {
            float d = g_dis[gr];
            float4 v0 = make_float4(acc[i][0] * d, acc[i][1] * d, acc[i][2] * d, acc[i][3] * d);
            float4 v1 = make_float4(acc[i][4] * d, acc[i][5] * d, acc[i][6] * d, acc[i][7] * d);
            *(float4*)(H + (size_t)gr * BN + tx * 4)          = v0;
            *(float4*)(H + (size_t)gr * BN + BN / 2 + tx * 4) = v1;
        }
    }
}

// ---------------------------------------------------------------------------
// Gather, layer 1: warp per node, lane covers 4 of 128 floats.
// agg1[c] = relu(dis[c] * (sum_{r in N(c)} h1[r] + h1[c]) + b1)
// ---------------------------------------------------------------------------
__global__ void gather1_kernel(const float* __restrict__ b1, int n) {
    int w = (blockIdx.x * blockDim.x + threadIdx.x) >> 5;
    if (w >= n) return;
    int lane = threadIdx.x & 31;
    int s = g_off[w], e = g_off[w + 1];
    const float4* h = (const float4*)g_h1;
    float4 a0 = make_float4(0.f, 0.f, 0.f, 0.f), a1 = a0;
    int i = s;
    for (; i + 1 < e; i += 2) {
        int r0 = __ldg(g_csr + i), r1 = __ldg(g_csr + i + 1);
        float4 v0 = h[(size_t)r0 * 32 + lane];
        float4 v1 = h[(size_t)r1 * 32 + lane];
        a0.x += v0.x; a0.y += v0.y; a0.z += v0.z; a0.w += v0.w;
        a1.x += v1.x; a1.y += v1.y; a1.z += v1.z; a1.w += v1.w;
    }
    if (i < e) {
        int r0 = __ldg(g_csr + i);
        float4 v0 = h[(size_t)r0 * 32 + lane];
        a0.x += v0.x; a0.y += v0.y; a0.z += v0.z; a0.w += v0.w;
    }
    float4 sv = h[(size_t)w * 32 + lane];
    float d = g_dis[w];
    float4 b = ((const float4*)b1)[lane];
    float4 r;
    r.x = fmaxf(fmaf(a0.x + a1.x + sv.x, d, b.x), 0.f);
    r.y = fmaxf(fmaf(a0.y + a1.y + sv.y, d, b.y), 0.f);
    r.z = fmaxf(fmaf(a0.z + a1.z + sv.z, d, b.z), 0.f);
    r.w = fmaxf(fmaf(a0.w + a1.w + sv.w, d, b.w), 0.f);
    ((float4*)g_agg1)[(size_t)w * 32 + lane] = r;
}

// Gather, layer 2: warp per node, lane covers 2 of 64 floats -> d_out.
__global__ void gather2_kernel(const float* __restrict__ b2, float* __restrict__ dout, int n) {
    int w = (blockIdx.x * blockDim.x + threadIdx.x) >> 5;
    if (w >= n) return;
    int lane = threadIdx.x & 31;
    int s = g_off[w], e = g_off[w + 1];
    const float2* h = (const float2*)g_h2;
    float2 a0 = make_float2(0.f, 0.f), a1 = a0;
    int i = s;
    for (; i + 1 < e; i += 2) {
        int r0 = __ldg(g_csr + i), r1 = __ldg(g_csr + i + 1);
        float2 v0 = h[(size_t)r0 * 32 + lane];
        float2 v1 = h[(size_t)r1 * 32 + lane];
        a0.x += v0.x; a0.y += v0.y;
        a1.x += v1.x; a1.y += v1.y;
    }
    if (i < e) {
        int r0 = __ldg(g_csr + i);
        float2 v0 = h[(size_t)r0 * 32 + lane];
        a0.x += v0.x; a0.y += v0.y;
    }
    float2 sv = h[(size_t)w * 32 + lane];
    float d = g_dis[w];
    float2 b = ((const float2*)b2)[lane];
    float2 r;
    r.x = fmaf(a0.x + a1.x + sv.x, d, b.x);
    r.y = fmaf(a0.y + a1.y + sv.y, d, b.y);
    ((float2*)dout)[(size_t)w * 32 + lane] = r;
}

// ---------------------------------------------------------------------------
extern "C" void kernel_launch(void* const* d_in, const int* in_sizes, int n_in,
                              void* d_out, int out_size) {
    const float* x  = (const float*)d_in[0];
    const int*   ei = (const int*)  d_in[1];
    const float* W1 = (const float*)d_in[2];
    const float* b1 = (const float*)d_in[3];
    const float* W2 = (const float*)d_in[4];
    const float* b2 = (const float*)d_in[5];
    float* out = (float*)d_out;

    int n = in_sizes[0] / D1;
    int E = in_sizes[1] / 2;
    const int* row = ei;
    const int* col = ei + E;
    int nb = (n + SCAN_B - 1) / SCAN_B;

    const int TB = 256;
    zero_kernel<<<(n + TB - 1) / TB, TB>>>(n);
    deg_kernel<<<(E + TB - 1) / TB, TB>>>(col, E);
    dis_kernel<<<(n + TB - 1) / TB, TB>>>(n);

    scan1_kernel<<<nb, SCAN_B>>>(n);
    scan2_kernel<<<1, SCAN_B>>>(nb);
    scan3_kernel<<<(n + 1 + TB - 1) / TB, TB>>>(n, E);
    fill_kernel<<<(E + TB - 1) / TB, TB>>>(row, col, E);

    sgemm_kernel<128, 128, 16, 1><<<(n + 127) / 128, TB>>>(x, W1, n);
    gather1_kernel<<<(n * 32 + TB - 1) / TB, TB>>>(b1, n);

    sgemm_kernel<256, 64, 16, 2><<<(n + 255) / 256, TB>>>(nullptr, W2, n);
    gather2_kernel<<<(n * 32 + TB - 1) / TB, TB>>>(b2, out, n);
}